// round 14
// baseline (speedup 1.0000x reference)
#include <cuda_runtime.h>
#include <cuda_bf16.h>
#include <cstdint>

// ---------------- problem constants ------------------------------------------
#define NN    5120
#define NPG   40
#define BB    128
#define LPP   512
#define MAXNN 45
#define PROTD 1280
#define NPROT 229
#define SLOTS 128

// ---------------- device scratch (static, no allocation) ---------------------
__device__ float g_deg[NN];
__device__ float g_xw[NN * 256];
__device__ float g_ha[NN * 256];
__device__ float g_hb[NN * 256];
__device__ float g_xp[NN * 96];
__device__ float g_hdense[BB * MAXNN * 256];   // pad rows stay zero
__device__ float g_fc[BB * MAXNN * 1024];
__device__ float g_hd[BB * MAXNN * 128];
__device__ float g_t1[BB * LPP * 128];
__device__ float g_t2[BB * LPP * 128];
__device__ float g_C[BB * LPP * 45];
__device__ float g_Wcx[BB * 32 * 45];
__device__ float g_Wpt[BB * 32 * 512];
__device__ float g_Hc[BB * 32 * 45];
__device__ float g_Hp[BB * 32 * 512];
__device__ float g_ac[BB * 45];
__device__ float g_ap[BB * 512];
__device__ float g_cp[BB * 256];
__device__ float g_c1[BB * 1024];
__device__ float g_c2[BB * 512];
// protein dedup
__device__ int g_present[NPROT];
__device__ int g_slotof[NPROT];
__device__ int g_pid_of_slot[NPROT];
__device__ int g_map[BB];
__device__ int g_cnt[1];
// gather table
__device__ int g_cur[NN];
__device__ int g_slots[NN * SLOTS];
// tf32-rounded weights
__device__ float g_rB1[1280 * 128];
__device__ float g_rB2[128 * 128];
__device__ float g_rWb[128 * 128];
__device__ float g_rW2[128 * 128];
__device__ float g_rW3[128 * 256];
__device__ float g_rFc1[256 * 1024];
__device__ float g_rFc2[1024 * 128];
__device__ float g_rCat1[256 * 1024];
__device__ float g_rCat2[1024 * 512];
__device__ float g_rWp[32 * 128];
__device__ float g_rW1p[96 * 128];

// ---------------- tf32 rna helper --------------------------------------------
__device__ __forceinline__ float rna_tf32(float v) {
    uint32_t u;
    asm("cvt.rna.tf32.f32 %0, %1;" : "=r"(u) : "f"(v));
    return __uint_as_float(u);
}

// ---------------- prep: dedup + degree/cursor init ----------------------------
__global__ void prep_k(const int* __restrict__ tgt) {
    int i = blockIdx.x * 256 + threadIdx.x;
    if (i < NN) { g_deg[i] = 1.0f; g_cur[i] = 0; }
    if (blockIdx.x == 0) {
        int t = threadIdx.x;
        if (t < NPROT) g_present[t] = 0;
        __syncthreads();
        if (t < BB) g_present[tgt[t]] = 1;
        __syncthreads();
        if (t == 0) {
            int c = 0;
            for (int p = 0; p < NPROT; p++) {
                g_slotof[p] = c;
                if (g_present[p]) { g_pid_of_slot[c] = p; c++; }
            }
            g_cnt[0] = c;
        }
        __syncthreads();
        if (t < BB) g_map[t] = g_slotof[tgt[t]];
    }
}

// ---------------- fused weight rna-rounding ----------------------------------
#define RN_E0 163840
#define RN_E1 180224
#define RN_E2 196608
#define RN_E3 212992
#define RN_E4 245760
#define RN_E5 507904
#define RN_E6 638976
#define RN_E7 901120
#define RN_E8 1425408
#define RN_E9 1429504
__global__ void rndall_k(const float* b1, const float* b2, const float* wb,
                         const float* w2, const float* w3, const float* f1,
                         const float* f2, const float* c1, const float* c2,
                         const float* wp) {
    int i = blockIdx.x * 256 + threadIdx.x;
    if (i >= RN_E9) return;
    const float* s; float* d; int off;
    if      (i < RN_E0) { s = b1; d = g_rB1;   off = 0; }
    else if (i < RN_E1) { s = b2; d = g_rB2;   off = RN_E0; }
    else if (i < RN_E2) { s = wb; d = g_rWb;   off = RN_E1; }
    else if (i < RN_E3) { s = w2; d = g_rW2;   off = RN_E2; }
    else if (i < RN_E4) { s = w3; d = g_rW3;   off = RN_E3; }
    else if (i < RN_E5) { s = f1; d = g_rFc1;  off = RN_E4; }
    else if (i < RN_E6) { s = f2; d = g_rFc2;  off = RN_E5; }
    else if (i < RN_E7) { s = c1; d = g_rCat1; off = RN_E6; }
    else if (i < RN_E8) { s = c2; d = g_rCat2; off = RN_E7; }
    else                { s = wp; d = g_rWp;   off = RN_E8; }
    int j = i - off;
    d[j] = rna_tf32(s[j]);
}

// ---------------- pad x and gW1 ------------------------------------------------
#define PAD_NX (NN * 96)
#define PAD_TOT (PAD_NX + 96 * 128)
__global__ void pad_k(const float* __restrict__ x, const float* __restrict__ w1) {
    int i = blockIdx.x * 256 + threadIdx.x;
    if (i < PAD_NX) {
        int r = i / 96, c = i - r * 96;
        g_xp[i] = (c < 78) ? rna_tf32(x[r * 78 + c]) : 0.0f;
    } else if (i < PAD_TOT) {
        int j = i - PAD_NX;
        int k = j >> 7, n = j & 127;
        g_rW1p[j] = (k < 78) ? rna_tf32(w1[k * 128 + n]) : 0.0f;
    }
}

// ---------------- graph structure (deg + slot fill fused) ---------------------
__global__ void edges_k(const int* __restrict__ src, const int* __restrict__ dst, int E) {
    int e = blockIdx.x * blockDim.x + threadIdx.x;
    if (e < E) {
        int d = dst[e];
        atomicAdd(&g_deg[d], 1.0f);
        int pos = atomicAdd(&g_cur[d], 1);
        if (pos < SLOTS) g_slots[d * SLOTS + pos] = src[e];
    }
}

// out = rna(relu(self[d] + sum_e xw[src_e]*c_e + bias)); optional dense remap
__global__ void gcn_post_k(const float* __restrict__ xw, const float* __restrict__ self,
                           const float* __restrict__ bias, float* __restrict__ out,
                           int F, int dense) {
    int d = blockIdx.x;
    int f = threadIdx.x;
    float rd = rsqrtf(g_deg[d]);
    float acc = self[(long)d * F + f];
    int n = g_cur[d];
    const int* sl = &g_slots[d * SLOTS];
    for (int e = 0; e < n; e++) {
        int s = sl[e];
        acc += xw[(long)s * F + f] * (rsqrtf(g_deg[s]) * rd);
    }
    int row = d;
    if (dense) { int b = d / NPG; row = b * MAXNN + (d - b * NPG); }
    out[(long)row * F + f] = rna_tf32(fmaxf(acc + bias[f], 0.0f));
}

// ---------------- mma/cp.async helpers ----------------------------------------
__device__ __forceinline__ void mma_tf32(float* c, uint32_t a0, uint32_t a1,
                                         uint32_t a2, uint32_t a3,
                                         uint32_t b0, uint32_t b1) {
    asm volatile(
        "mma.sync.aligned.m16n8k8.row.col.f32.tf32.tf32.f32 "
        "{%0,%1,%2,%3}, {%4,%5,%6,%7}, {%8,%9}, {%0,%1,%2,%3};"
        : "+f"(c[0]), "+f"(c[1]), "+f"(c[2]), "+f"(c[3])
        : "r"(a0), "r"(a1), "r"(a2), "r"(a3), "r"(b0), "r"(b1));
}
__device__ __forceinline__ void cp16(float* dst, const float* src) {
    uint32_t sa = (uint32_t)__cvta_generic_to_shared(dst);
    asm volatile("cp.async.cg.shared.global [%0], [%1], 16;" :: "r"(sa), "l"(src));
}
__device__ __forceinline__ void cp_commit() {
    asm volatile("cp.async.commit_group;");
}
template <int NG> __device__ __forceinline__ void cp_wait() {
    asm volatile("cp.async.wait_group %0;" :: "n"(NG));
}

// ---------------- unified M64xN128 tf32 GEMM (3-stage, 3 CTAs/SM) -------------
// A smem: 64 rows x 32 floats, XOR chunk swizzle (chunk ^ (row&7)), stride 32.
// B smem: 32 rows x 128 floats, stride 136 (conflict-free frag reads).
#define AS_ST 32
#define BS_ST 136
#define STG (64 * AS_ST + 32 * BS_ST)            // 6400 floats = 25600 B
#define GU_SMEM_BYTES (3 * STG * 4)              // 76800 B -> 3 CTAs/SM

__global__ void __launch_bounds__(256, 3)
gemmu_k(const float* __restrict__ A, const float* __restrict__ W,
        const float* __restrict__ bias, float* __restrict__ Cout,
        int M, int K, int N, int act,
        const int* __restrict__ gidx, const int* __restrict__ cntp,
        int fixA, int rndC, float* __restrict__ C2,
        const float* __restrict__ degp) {
    const int bm = blockIdx.y << 6, bn = blockIdx.x << 7;
    if (cntp && bm >= cntp[0] * 512) return;

    extern __shared__ float sm[];
    float* Acur = sm;
    float* Bcur = sm + 64 * AS_ST;
    float* Anxt = sm + STG;
    float* Bnxt = Anxt + 64 * AS_ST;
    float* Afut = sm + 2 * STG;
    float* Bfut = Afut + 64 * AS_ST;

    const int tid  = threadIdx.x;
    const int warp = tid >> 5, lane = tid & 31;
    const int wm = (warp & 1) << 5;     // 2 warp-rows x 32
    const int wn = (warp >> 1) << 5;    // 4 warp-cols x 32
    const int gid = lane >> 2, tig = lane & 3;
    const uint32_t afix = fixA ? 0x1000u : 0u;

    float acc[2][4][4];
#pragma unroll
    for (int i = 0; i < 2; i++)
#pragma unroll
        for (int j = 0; j < 4; j++)
#pragma unroll
            for (int q = 0; q < 4; q++) acc[i][j][q] = 0.0f;

    // A: 64 rows x 8 chunks = 512 cp16 -> 2 per thread; swizzled chunk store
    int a_m[2], a_soff[2];
    long a_row[2];
#pragma unroll
    for (int i = 0; i < 2; i++) {
        int lin = tid + (i << 8);
        int m = lin >> 3, ck = lin & 7;
        a_m[i] = m;
        a_soff[i] = m * AS_ST + ((ck ^ (m & 7)) << 2);
        int gm = bm + m;
        a_row[i] = gidx ? ((long)gidx[gm >> 9] * 512 + (gm & 511)) : (long)gm;
    }
    // B: 32 rows x 32 chunks = 1024 cp16 -> 4 per thread
    int b_k[4], b_n4[4];
#pragma unroll
    for (int i = 0; i < 4; i++) {
        int lin = tid + (i << 8);
        b_k[i] = lin >> 5;
        b_n4[i] = (lin & 31) << 2;
    }

    const int KT = K >> 5;
    auto load_tile = [&](int k0, float* As, float* Bs) {
#pragma unroll
        for (int i = 0; i < 2; i++)
            cp16(As + a_soff[i],
                 A + a_row[i] * (long)K + k0 + (((a_soff[i] >> 2) & 7) ^ 0, ((tid + (i << 8)) & 7) << 2));
#pragma unroll
        for (int i = 0; i < 4; i++)
            cp16(Bs + b_k[i] * BS_ST + b_n4[i],
                 W + (long)(k0 + b_k[i]) * N + bn + b_n4[i]);
        cp_commit();
    };
    // NOTE: the A global offset must be the UNswizzled chunk ((lin&7)<<2).
    // Rewritten explicitly below to avoid the comma-expression above.
    auto load_tile2 = [&](int k0, float* As, float* Bs) {
#pragma unroll
        for (int i = 0; i < 2; i++) {
            int lin = tid + (i << 8);
            int gk4 = (lin & 7) << 2;
            cp16(As + a_soff[i], A + a_row[i] * (long)K + k0 + gk4);
        }
#pragma unroll
        for (int i = 0; i < 4; i++)
            cp16(Bs + b_k[i] * BS_ST + b_n4[i],
                 W + (long)(k0 + b_k[i]) * N + bn + b_n4[i]);
        cp_commit();
    };
    (void)load_tile;

    load_tile2(0, Acur, Bcur);
    load_tile2(32, Anxt, Bnxt);

    for (int kt = 0; kt < KT; kt++) {
        cp_wait<1>();
        __syncthreads();
        if (kt + 2 < KT) load_tile2((kt + 2) << 5, Afut, Bfut);
        else             cp_commit();
        float* As = Acur;
        float* Bs = Bcur;

#pragma unroll
        for (int ks = 0; ks < 4; ks++) {
            const int kk = ks << 3;
            const int c0 = kk >> 2;          // chunk of k = kk..kk+3
            uint32_t bf[4][2];
#pragma unroll
            for (int nt = 0; nt < 4; nt++) {
                int col = wn + (nt << 3) + gid;
                bf[nt][0] = __float_as_uint(Bs[(kk + tig) * BS_ST + col]);
                bf[nt][1] = __float_as_uint(Bs[(kk + tig + 4) * BS_ST + col]);
            }
#pragma unroll
            for (int mt = 0; mt < 2; mt++) {
                int r0 = wm + (mt << 4) + gid;      // row, (row&7)==(gid&7)
                int r1 = r0 + 8;
                int sw0 = r0 & 7, sw1 = r1 & 7;     // equal, but keep explicit
                uint32_t a0 = __float_as_uint(As[r0 * AS_ST + (((c0)     ^ sw0) << 2) + tig]) + afix;
                uint32_t a1 = __float_as_uint(As[r1 * AS_ST + (((c0)     ^ sw1) << 2) + tig]) + afix;
                uint32_t a2 = __float_as_uint(As[r0 * AS_ST + (((c0 + 1) ^ sw0) << 2) + tig]) + afix;
                uint32_t a3 = __float_as_uint(As[r1 * AS_ST + (((c0 + 1) ^ sw1) << 2) + tig]) + afix;
#pragma unroll
                for (int nt = 0; nt < 4; nt++)
                    mma_tf32(acc[mt][nt], a0, a1, a2, a3, bf[nt][0], bf[nt][1]);
            }
        }
        float* ta = Acur; Acur = Anxt; Anxt = Afut; Afut = ta;
        float* tb = Bcur; Bcur = Bnxt; Bnxt = Bfut; Bfut = tb;
    }

#pragma unroll
    for (int mt = 0; mt < 2; mt++) {
        int r0 = bm + wm + (mt << 4) + gid;
        float id0 = 0.0f, id1 = 0.0f;
        if (C2) { id0 = 1.0f / degp[r0]; id1 = 1.0f / degp[r0 + 8]; }
#pragma unroll
        for (int nt = 0; nt < 4; nt++) {
            int c = bn + wn + (nt << 3) + (tig << 1);
            float v0 = acc[mt][nt][0], v1 = acc[mt][nt][1];
            float v2 = acc[mt][nt][2], v3 = acc[mt][nt][3];
            if (bias) {
                float b0 = bias[c], b1 = bias[c + 1];
                v0 += b0; v1 += b1; v2 += b0; v3 += b1;
            }
            if (act) {
                v0 = fmaxf(v0, 0.0f); v1 = fmaxf(v1, 0.0f);
                v2 = fmaxf(v2, 0.0f); v3 = fmaxf(v3, 0.0f);
            }
            if (rndC) {
                v0 = rna_tf32(v0); v1 = rna_tf32(v1);
                v2 = rna_tf32(v2); v3 = rna_tf32(v3);
            }
            *(float2*)&Cout[(long)r0 * N + c] = make_float2(v0, v1);
            *(float2*)&Cout[(long)(r0 + 8) * N + c] = make_float2(v2, v3);
            if (C2) {
                *(float2*)&C2[(long)r0 * N + c] = make_float2(v0 * id0, v1 * id0);
                *(float2*)&C2[(long)(r0 + 8) * N + c] = make_float2(v2 * id1, v3 * id1);
            }
        }
    }
}

// ---------------- co-attention: C via tensor cores ----------------------------
#define CC_SMEM ((128 * 132 + 64 * 132) * 4)
__global__ void __launch_bounds__(256)
coattC_mma_k(const float* __restrict__ TW, const float* __restrict__ hd,
             float* __restrict__ C) {
    int b = blockIdx.y;
    int l0 = blockIdx.x << 7;
    int slot = g_map[b];
    extern __shared__ float sm[];
    float* As = sm;
    float* Bs = sm + 128 * 132;
    int tid = threadIdx.x;

    const float* Ab = TW + ((long)slot * 512 + l0) * 128;
    for (int i = tid; i < 128 * 32; i += 256) {
        int r = i >> 5, c4 = (i & 31) << 2;
        *(float4*)&As[r * 132 + c4] = *(const float4*)(Ab + r * 128 + c4);
    }
    const float* Bb = hd + (long)b * 45 * 128;
    for (int i = tid; i < 64 * 32; i += 256) {
        int r = i >> 5, c4 = (i & 31) << 2;
        float4 v = make_float4(0.f, 0.f, 0.f, 0.f);
        if (r < 45) v = *(const float4*)(Bb + r * 128 + c4);
        *(float4*)&Bs[r * 132 + c4] = v;
    }
    __syncthreads();

    int warp = tid >> 5, lane = tid & 31;
    int wm = (warp & 1) << 6;
    int wn = (warp >> 1) << 4;
    int gid = lane >> 2, tig = lane & 3;
    float acc[4][2][4];
#pragma unroll
    for (int i = 0; i < 4; i++)
#pragma unroll
        for (int j = 0; j < 2; j++)
#pragma unroll
            for (int q = 0; q < 4; q++) acc[i][j][q] = 0.0f;

#pragma unroll
    for (int kk = 0; kk < 128; kk += 8) {
        uint32_t bf[2][2];
#pragma unroll
        for (int nt = 0; nt < 2; nt++) {
            int col = wn + (nt << 3) + gid;
            bf[nt][0] = __float_as_uint(Bs[col * 132 + kk + tig]);
            bf[nt][1] = __float_as_uint(Bs[col * 132 + kk + tig + 4]);
        }
#pragma unroll
        for (int mt = 0; mt < 4; mt++) {
            int row = wm + (mt << 4) + gid;
            uint32_t a0 = __float_as_uint(As[row * 132 + kk + tig]);
            uint32_t a1 = __float_as_uint(As[(row + 8) * 132 + kk + tig]);
            uint32_t a2 = __float_as_uint(As[row * 132 + kk + tig + 4]);
            uint32_t a3 = __float_as_uint(As[(row + 8) * 132 + kk + tig + 4]);
#pragma unroll
            for (int nt = 0; nt < 2; nt++)
                mma_tf32(acc[mt][nt], a0, a1, a2, a3, bf[nt][0], bf[nt][1]);
        }
    }

#pragma unroll
    for (int mt = 0; mt < 4; mt++) {
        int l = l0 + wm + (mt << 4) + gid;
        float* d0 = &C[((long)b * 512 + l) * 45];
        float* d8 = &C[((long)b * 512 + l + 8) * 45];
#pragma unroll
        for (int nt = 0; nt < 2; nt++) {
            int s = wn + (nt << 3) + (tig << 1);
            if (s < 45)     d0[s]     = tanhf(acc[mt][nt][0]);
            if (s + 1 < 45) d0[s + 1] = tanhf(acc[mt][nt][1]);
            if (s < 45)     d8[s]     = tanhf(acc[mt][nt][2]);
            if (s + 1 < 45) d8[s + 1] = tanhf(acc[mt][nt][3]);
        }
    }
}

// ---------------- co-attention: Wpt per distinct protein slot -----------------
#define WP_SMEM ((128 * 132 + 32 * 132) * 4)
__global__ void __launch_bounds__(256)
wptslot_mma_k(const float* __restrict__ t2, const float* __restrict__ Wp,
              float* __restrict__ Wpt) {
    int slot = blockIdx.y;
    if (slot >= g_cnt[0]) return;
    int l0 = blockIdx.x << 7;
    extern __shared__ float sm[];
    float* As = sm;
    float* Bs = sm + 128 * 132;
    int tid = threadIdx.x;

    const float* Ab = t2 + ((long)slot * 512 + l0) * 128;
    for (int i = tid; i < 128 * 32; i += 256) {
        int r = i >> 5, c4 = (i & 31) << 2;
        *(float4*)&As[r * 132 + c4] = *(const float4*)(Ab + r * 128 + c4);
    }
    for (int i = tid; i < 32 * 32; i += 256) {
        int r = i >> 5, c4 = (i & 31) << 2;
        *(float4*)&Bs[r * 132 + c4] = *(const float4*)(Wp + r * 128 + c4);
    }
    __syncthreads();

    int warp = tid >> 5, lane = tid & 31;
    int wm = (warp & 1) << 6;
    int wn = (warp >> 1) << 3;
    int gid = lane >> 2, tig = lane & 3;
    float acc[4][4];
#pragma unroll
    for (int i = 0; i < 4; i++)
#pragma unroll
        for (int q = 0; q < 4; q++) acc[i][q] = 0.0f;

#pragma unroll
    for (int kk = 0; kk < 128; kk += 8) {
        int col = wn + gid;
        uint32_t b0 = __float_as_uint(Bs[col * 132 + kk + tig]);
        uint32_t b1 = __float_as_uint(Bs[col * 132 + kk + tig + 4]);
#pragma unroll
        for (int mt = 0; mt < 4; mt++) {
            int row = wm + (mt << 4) + gid;
            uint32_t a0 = __float_as_uint(As[row * 132 + kk + tig]);
            uint32_t a1 = __float_as_uint(As[(row + 8) * 132 + kk + tig]);
            uint32_t a2 = __float_as_uint(As[row * 132 + kk + tig + 4]);
            uint32_t a3 = __float_as_uint(As[(row + 8) * 132 + kk + tig + 4]);
            mma_tf32(acc[mt], a0, a1, a2, a3, b0, b1);
        }
    }

#pragma unroll
    for (int mt = 0; mt < 4; mt++) {
        int l = l0 + wm + (mt << 4) + gid;
        int n = wn + (tig << 1);
        Wpt[((long)slot * 32 + n)     * 512 + l]     = acc[mt][0];
        Wpt[((long)slot * 32 + n + 1) * 512 + l]     = acc[mt][1];
        Wpt[((long)slot * 32 + n)     * 512 + l + 8] = acc[mt][2];
        Wpt[((long)slot * 32 + n + 1) * 512 + l + 8] = acc[mt][3];
    }
}

// Wcx[b,k,s] = sum_m W_c[k,m] * hd[b,s,m]
__global__ void __launch_bounds__(256)
wcx_k(const float* __restrict__ Wc, const float* __restrict__ hd,
      float* __restrict__ Wcx) {
    int b = blockIdx.x;
    __shared__ float Wcs[32][132];
    __shared__ float hds[45][132];
    int tid = threadIdx.x;
    for (int idx = tid; idx < 32 * 32; idx += 256) {
        int r = idx >> 5, c = (idx & 31) << 2;
        float4 v = *(const float4*)(Wc + r * 128 + c);
        Wcs[r][c] = v.x; Wcs[r][c + 1] = v.y; Wcs[r][c + 2] = v.z; Wcs[r][c + 3] = v.w;
    }
    const float* hdb = hd + (long)b * 45 * 128;
    for (int idx = tid; idx < 45 * 32; idx += 256) {
        int r = idx >> 5, c = (idx & 31) << 2;
        float4 v = *(const float4*)(hdb + r * 128 + c);
        hds[r][c] = v.x; hds[r][c + 1] = v.y; hds[r][c + 2] = v.z; hds[r][c + 3] = v.w;
    }
    __syncthreads();
    for (int o = tid; o < 32 * 45; o += 256) {
        int k = o / 45, s = o - k * 45;
        float a = 0.0f;
        for (int m = 0; m < 128; m += 4) {
            float4 wv = *(const float4*)&Wcs[k][m];
            float4 hv = *(const float4*)&hds[s][m];
            a += wv.x * hv.x + wv.y * hv.y + wv.z * hv.z + wv.w * hv.w;
        }
        Wcx[((long)b * 32 + k) * 45 + s] = a;
    }
}

// Hc[b,k,s] = tanh(Wcx[b,k,s] + sum_l Wpt[slot,k,l]*C[b,l,s])
__global__ void __launch_bounds__(256)
hc_k(const float* __restrict__ Wpt, const float* __restrict__ C,
     const float* __restrict__ Wcx, float* __restrict__ Hc) {
    int b = blockIdx.x;
    int slot = g_map[b];
    __shared__ float Cc[64][48];
    __shared__ float Wptc[32][64];
    int tid = threadIdx.x;
    float acc[6] = {0, 0, 0, 0, 0, 0};
    for (int lc = 0; lc < 512; lc += 64) {
        for (int idx = tid; idx < 32 * 64; idx += 256) {
            int k = idx >> 6, li = idx & 63;
            Wptc[k][li] = Wpt[((long)slot * 32 + k) * 512 + lc + li];
        }
        for (int idx = tid; idx < 64 * 48; idx += 256) {
            int li = idx / 48, s = idx - li * 48;
            Cc[li][s] = (s < 45) ? C[((long)b * 512 + lc + li) * 45 + s] : 0.0f;
        }
        __syncthreads();
#pragma unroll
        for (int i = 0; i < 6; i++) {
            int o = tid + (i << 8);
            if (o < 32 * 45) {
                int k = o / 45, s = o - k * 45;
                float a = acc[i];
#pragma unroll 8
                for (int li = 0; li < 64; li++) a += Wptc[k][li] * Cc[li][s];
                acc[i] = a;
            }
        }
        __syncthreads();
    }
#pragma unroll
    for (int i = 0; i < 6; i++) {
        int o = tid + (i << 8);
        if (o < 32 * 45) {
            int k = o / 45, s = o - k * 45;
            long idx = ((long)b * 32 + k) * 45 + s;
            Hc[idx] = tanhf(acc[i] + Wcx[idx]);
        }
    }
}

// Hp[b,k,l] = tanh(Wpt[slot,k,l] + sum_s Wcx[b,k,s]*C[b,l,s])
__global__ void __launch_bounds__(256)
hp_k(const float* __restrict__ Wpt, const float* __restrict__ C,
     const float* __restrict__ Wcx, float* __restrict__ Hp) {
    int b = blockIdx.y;
    int slot = g_map[b];
    int l0 = blockIdx.x << 7;
    __shared__ float Wcxs[32][48];
    __shared__ float Cs[128][48];
    int tid = threadIdx.x;
    for (int idx = tid; idx < 32 * 48; idx += 256) {
        int k = idx / 48, s = idx - k * 48;
        Wcxs[k][s] = (s < 45) ? Wcx[((long)b * 32 + k) * 45 + s] : 0.0f;
    }
    for (int idx = tid; idx < 128 * 48; idx += 256) {
        int li = idx / 48, s = idx - li * 48;
        Cs[li][s] = (s < 45) ? C[((long)b * 512 + l0 + li) * 45 + s] : 0.0f;
    }
    __syncthreads();
#pragma unroll
    for (int i = 0; i < 16; i++) {
        int o = tid + (i << 8);
        int k = o >> 7, l = o & 127;
        float a = Wpt[((long)slot * 32 + k) * 512 + l0 + l];
#pragma unroll 8
        for (int s = 0; s < 48; s++) a += Wcxs[k][s] * Cs[l][s];
        Hp[((long)b * 32 + k) * 512 + l0 + l] = tanhf(a);
    }
}

__global__ void ac_k(const float* __restrict__ Hc, const float* __restrict__ whc,
                     float* __restrict__ ac) {
    int b = blockIdx.x, s = threadIdx.x;
    __shared__ float red[64];
    float v = -3.0e38f;
    if (s < 45) {
        float a = 0.0f;
#pragma unroll
        for (int k = 0; k < 32; k++) a += whc[k] * Hc[((long)b * 32 + k) * 45 + s];
        v = a;
    }
    red[s] = v;
    __syncthreads();
    for (int off = 32; off > 0; off >>= 1) {
        if (s < off) red[s] = fmaxf(red[s], red[s + off]);
        __syncthreads();
    }
    float mx = red[0];
    __syncthreads();
    float e = (s < 45) ? expf(v - mx) : 0.0f;
    red[s] = e;
    __syncthreads();
    for (int off = 32; off > 0; off >>= 1) {
        if (s < off) red[s] += red[s + off];
        __syncthreads();
    }
    float inv = 1.0f / red[0];
    if (s < 45) ac[b * 45 + s] = e * inv;
}

__global__ void ap_k(const float* __restrict__ Hp, const float* __restrict__ whp,
                     float* __restrict__ ap) {
    int b = blockIdx.x, t = threadIdx.x;
    __shared__ float red[256];
    float v0 = 0.0f, v1 = 0.0f;
#pragma unroll
    for (int k = 0; k < 32; k++) {
        const float* row = Hp + ((long)b * 32 + k) * 512;
        float w = whp[k];
        v0 += w * row[t];
        v1 += w * row[t + 256];
    }
    red[t] = fmaxf(v0, v1);
    __syncthreads();
    for (int off = 128; off > 0; off >>= 1) {
        if (t < off) red[t] = fmaxf(red[t], red[t + off]);
        __syncthreads();
    }
    float mx = red[0];
    __syncthreads();
    float e0 = expf(v0 - mx), e1 = expf(v1 - mx);
    red[t] = e0 + e1;
    __syncthreads();
    for (int off = 128; off > 0; off >>= 1) {
        if (t < off) red[t] += red[t + off];
        __syncthreads();
    }
    float inv = 1.0f / red[0];
    ap[b * 512 + t] = e0 * inv;
    ap[b * 512 + t + 256] = e1 * inv;
}

__global__ void cp_k(const float* __restrict__ ac, const float* __restrict__ ap,
                     const float* __restrict__ hd, const float* __restrict__ t2,
                     float* __restrict__ cp) {
    int b = blockIdx.x, m = threadIdx.x;
    int slot = g_map[b];
    __shared__ float acs[45];
    __shared__ float aps[512];
    if (m < 45) acs[m] = ac[b * 45 + m];
    for (int i = m; i < 512; i += 128) aps[i] = ap[b * 512 + i];
    __syncthreads();
    float c = 0.0f;
    for (int s = 0; s < 45; s++) c += acs[s] * hd[((long)b * 45 + s) * 128 + m];
    const float* t2b = t2 + (long)slot * 512 * 128;
    float p = 0.0f;
    for (int l = 0; l < 512; l++) p += aps[l] * t2b[l * 128 + m];
    cp[b * 256 + m] = rna_tf32(c);
    cp[b * 256 + 128 + m] = rna_tf32(p);
}

__global__ void out_k(const float* __restrict__ c2, const float* __restrict__ outW,
                      const float* __restrict__ outb, float* __restrict__ out) {
    int b = blockIdx.x, t = threadIdx.x;
    __shared__ float red[128];
    float v = 0.0f;
    for (int i = t; i < 512; i += 128) v += c2[b * 512 + i] * outW[i];
    red[t] = v;
    __syncthreads();
    for (int off = 64; off > 0; off >>= 1) {
        if (t < off) red[t] += red[t + off];
        __syncthreads();
    }
    if (t == 0) out[b] = red[0] + outb[0];
}

// ---------------- host side ---------------------------------------------------
static inline float* symaddr(const void* sym) {
    void* p = nullptr;
    cudaGetSymbolAddress(&p, sym);
    return (float*)p;
}
static inline int* symaddri(const void* sym) {
    void* p = nullptr;
    cudaGetSymbolAddress(&p, sym);
    return (int*)p;
}

static inline void gemmu(const float* A, const float* W, const float* bias, float* C,
                         int M, int K, int N, int act,
                         const int* gidx, const int* cntp, int fixA, int rndC,
                         float* C2 = nullptr, const float* degp = nullptr) {
    dim3 g(N >> 7, M >> 6);
    gemmu_k<<<g, 256, GU_SMEM_BYTES>>>(A, W, bias, C, M, K, N, act,
                                       gidx, cntp, fixA, rndC, C2, degp);
}

extern "C" void kernel_launch(void* const* d_in, const int* in_sizes, int n_in,
                              void* d_out, int out_size) {
    const float* x      = (const float*)d_in[0];
    const int*   ei     = (const int*)d_in[1];
    const int*   tgt    = (const int*)d_in[2];
    const float* prot   = (const float*)d_in[4];
    const float* gW1    = (const float*)d_in[5];
    const float* gb1    = (const float*)d_in[6];
    const float* gW2    = (const float*)d_in[7];
    const float* gb2    = (const float*)d_in[8];
    const float* gW3    = (const float*)d_in[9];
    const float* gb3    = (const float*)d_in[10];
    const float* fc1W   = (const float*)d_in[11];
    const float* fc1b   = (const float*)d_in[12];
    const float* fc2W   = (const float*)d_in[13];
    const float* fc2b   = (const float*)d_in[14];
    const float* bert1W = (const float*)d_in[15];
    const float* bert1b = (const float*)d_in[16];
    const float* bert2W = (const float*)d_in[17];
    const float* bert2b = (const float*)d_in[18];
    const float* W_b    = (const float*)d_in[19];
    const float* W_c    = (const float*)d_in[20];
    const float* W_p    = (const float*)d_in[21];
    const float* w_hc   = (const float*)d_in[22];
    const float* w_hp   = (const float*)d_in[23];
    const float* cat1W  = (const float*)d_in[24];
    const float* cat1b  = (const float*)d_in[25];
    const float* cat2W  = (const float*)d_in[26];
    const float* cat2b  = (const float*)d_in[27];
    const float* outW   = (const float*)d_in[28];
    const float* outb   = (const float*)d_in[29];
    float* out = (float*)d_out;

    const int E = in_sizes[1] / 2;
    const int* src  = ei;
    const int* dstp = ei + E;

    float* p_deg    = symaddr(g_deg);
    float* p_xw     = symaddr(g_xw);
    float* p_ha     = symaddr(g_ha);
    float* p_hb     = symaddr(g_hb);
    float* p_xp     = symaddr(g_xp);
    float* p_hdense = symaddr(g_hdense);
    float* p_fc     = symaddr(g_fc);
    float* p_hd     = symaddr(g_hd);
    float* p_t1     = symaddr(g_t1);
    float* p_t2     = symaddr(g_t2);
    float* p_C      = symaddr(g_C);
    float* p_Wcx    = symaddr(g_Wcx);
    float* p_Wpt    = symaddr(g_Wpt);
    float* p_Hc     = symaddr(g_Hc);
    float* p_Hp     = symaddr(g_Hp);
    float* p_ac     = symaddr(g_ac);
    float* p_ap     = symaddr(g_ap);
    float* p_cp     = symaddr(g_cp);
    float* p_c1     = symaddr(g_c1);
    float* p_c2     = symaddr(g_c2);
    int*   p_pid    = symaddri(g_pid_of_slot);
    int*   p_cnt    = symaddri(g_cnt);
    float* p_rB1    = symaddr(g_rB1);
    float* p_rB2    = symaddr(g_rB2);
    float* p_rWb    = symaddr(g_rWb);
    float* p_rW2    = symaddr(g_rW2);
    float* p_rW3    = symaddr(g_rW3);
    float* p_rFc1   = symaddr(g_rFc1);
    float* p_rFc2   = symaddr(g_rFc2);
    float* p_rCat1  = symaddr(g_rCat1);
    float* p_rCat2  = symaddr(g_rCat2);
    float* p_rWp    = symaddr(g_rWp);
    float* p_rW1p   = symaddr(g_rW1p);

    cudaFuncSetAttribute(gemmu_k, cudaFuncAttributeMaxDynamicSharedMemorySize,
                         GU_SMEM_BYTES);
    cudaFuncSetAttribute(coattC_mma_k, cudaFuncAttributeMaxDynamicSharedMemorySize,
                         CC_SMEM);
    cudaFuncSetAttribute(wptslot_mma_k, cudaFuncAttributeMaxDynamicSharedMemorySize,
                         WP_SMEM);

    // 1: dedup + deg/cursor init
    prep_k<<<20, 256>>>(tgt);
    // 2: weight rna rounding
    rndall_k<<<(RN_E9 + 255) / 256, 256>>>(bert1W, bert2W, W_b, gW2, gW3,
                                           fc1W, fc2W, cat1W, cat2W, W_p);
    // 3: pad+round x and gW1
    pad_k<<<(PAD_TOT + 255) / 256, 256>>>(x, gW1);
    // 4: bert1 (ncu window target) — grid 1024, 3 CTAs/SM
    gemmu(prot, p_rB1, bert1b, p_t1, BB * LPP, PROTD, 128, 1, p_pid, p_cnt, 1, 1);
    // 5: graph structure
    edges_k<<<(E + 255) / 256, 256>>>(src, dstp, E);

    // GCN layer 1 (tensor, K=96 padded) + gather-post
    gemmu(p_xp, p_rW1p, nullptr, p_xw, NN, 96, 128, 0, nullptr, nullptr, 0, 0, p_ha, p_deg);
    gcn_post_k<<<NN, 128>>>(p_xw, p_ha, gb1, p_hb, 128, 0);

    // protein chain continues
    gemmu(p_t1, p_rB2, bert2b, p_t2, BB * LPP, 128, 128, 1, nullptr, p_cnt, 0, 1);
    gemmu(p_t2, p_rWb, nullptr, p_t1, BB * LPP, 128, 128, 0, nullptr, p_cnt, 0, 1);

    // GCN layer 2
    gemmu(p_hb, p_rW2, nullptr, p_xw, NN, 128, 128, 0, nullptr, nullptr, 0, 0, p_ha, p_deg);
    gcn_post_k<<<NN, 128>>>(p_xw, p_ha, gb2, p_ha, 128, 0);
    // GCN layer 3 (writes straight into dense layout)
    gemmu(p_ha, p_rW3, nullptr, p_xw, NN, 128, 256, 0, nullptr, nullptr, 0, 0, p_hb, p_deg);
    gcn_post_k<<<NN, 256>>>(p_xw, p_hb, gb3, p_hdense, 256, 1);

    // graph FC stack
    gemmu(p_hdense, p_rFc1, fc1b, p_fc, BB * MAXNN, 256, 1024, 1, nullptr, nullptr, 0, 1);
    gemmu(p_fc, p_rFc2, fc2b, p_hd, BB * MAXNN, 1024, 128, 1, nullptr, nullptr, 0, 1);

    // co-attention
    coattC_mma_k<<<dim3(4, BB), 256, CC_SMEM>>>(p_t1, p_hd, p_C);
    wptslot_mma_k<<<dim3(4, BB), 256, WP_SMEM>>>(p_t2, p_rWp, p_Wpt);
    wcx_k<<<BB, 256>>>(W_c, p_hd, p_Wcx);
    hc_k<<<BB, 256>>>(p_Wpt, p_C, p_Wcx, p_Hc);
    hp_k<<<dim3(4, BB), 256>>>(p_Wpt, p_C, p_Wcx, p_Hp);
    ac_k<<<BB, 64>>>(p_Hc, w_hc, p_ac);
    ap_k<<<BB, 256>>>(p_Hp, w_hp, p_ap);
    cp_k<<<BB, 128>>>(p_ac, p_ap, p_hd, p_t2, p_cp);

    // head
    gemmu(p_cp, p_rCat1, cat1b, p_c1, BB, 256, 1024, 1, nullptr, nullptr, 0, 1);
    gemmu(p_c1, p_rCat2, cat2b, p_c2, BB, 1024, 512, 1, nullptr, nullptr, 0, 0);
    out_k<<<BB, 128>>>(p_c2, outW, outb, out);
}

// round 16
// speedup vs baseline: 1.0293x; 1.0293x over previous
#include <cuda.h>
#include <cuda_runtime.h>
#include <cuda_bf16.h>
#include <cstdint>

// ---------------- problem constants ------------------------------------------
#define NN    5120
#define NPG   40
#define BB    128
#define LPP   512
#define MAXNN 45
#define PROTD 1280
#define NPROT 229
#define SLOTS 128

// ---------------- device scratch (static, no allocation) ---------------------
__device__ float g_deg[NN];
__device__ float g_xw[NN * 256];
__device__ float g_ha[NN * 256];
__device__ float g_hb[NN * 256];
__device__ float g_xp[NN * 96];
__device__ float g_hdense[BB * MAXNN * 256];   // pad rows stay zero
__device__ float g_fc[BB * MAXNN * 1024];
__device__ float g_hd[BB * MAXNN * 128];
__device__ float g_t1[BB * LPP * 128];
__device__ float g_t2[BB * LPP * 128];
__device__ float g_C[BB * LPP * 45];
__device__ float g_Wcx[BB * 32 * 45];
__device__ float g_Wpt[BB * 32 * 512];
__device__ float g_Hc[BB * 32 * 45];
__device__ float g_Hp[BB * 32 * 512];
__device__ float g_ac[BB * 45];
__device__ float g_ap[BB * 512];
__device__ float g_cp[BB * 256];
__device__ float g_c1[BB * 1024];
__device__ float g_c2[BB * 512];
// protein dedup
__device__ int g_present[NPROT];
__device__ int g_slotof[NPROT];
__device__ int g_pid_of_slot[NPROT];
__device__ int g_map[BB];
__device__ int g_cnt[1];
// gather table
__device__ int g_cur[NN];
__device__ int g_slots[NN * SLOTS];
// tf32-rounded weights
__device__ float g_rB1[1280 * 128];
__device__ float g_rB2[128 * 128];
__device__ float g_rWb[128 * 128];
__device__ float g_rW2[128 * 128];
__device__ float g_rW3[128 * 256];
__device__ float g_rFc1[256 * 1024];
__device__ float g_rFc2[1024 * 128];
__device__ float g_rCat1[256 * 1024];
__device__ float g_rCat2[1024 * 512];
__device__ float g_rWp[32 * 128];
__device__ float g_rW1p[96 * 128];

// ---------------- tf32 rna helper --------------------------------------------
__device__ __forceinline__ float rna_tf32(float v) {
    uint32_t u;
    asm("cvt.rna.tf32.f32 %0, %1;" : "=r"(u) : "f"(v));
    return __uint_as_float(u);
}

// ---------------- prep: dedup + degree/cursor init ----------------------------
__global__ void prep_k(const int* __restrict__ tgt) {
    int i = blockIdx.x * 256 + threadIdx.x;
    if (i < NN) { g_deg[i] = 1.0f; g_cur[i] = 0; }
    if (blockIdx.x == 0) {
        int t = threadIdx.x;
        if (t < NPROT) g_present[t] = 0;
        __syncthreads();
        if (t < BB) g_present[tgt[t]] = 1;
        __syncthreads();
        if (t == 0) {
            int c = 0;
            for (int p = 0; p < NPROT; p++) {
                g_slotof[p] = c;
                if (g_present[p]) { g_pid_of_slot[c] = p; c++; }
            }
            g_cnt[0] = c;
        }
        __syncthreads();
        if (t < BB) g_map[t] = g_slotof[tgt[t]];
    }
}

// ---------------- fused weight rna-rounding ----------------------------------
#define RN_E0 163840
#define RN_E1 180224
#define RN_E2 196608
#define RN_E3 212992
#define RN_E4 245760
#define RN_E5 507904
#define RN_E6 638976
#define RN_E7 901120
#define RN_E8 1425408
#define RN_E9 1429504
__global__ void rndall_k(const float* b1, const float* b2, const float* wb,
                         const float* w2, const float* w3, const float* f1,
                         const float* f2, const float* c1, const float* c2,
                         const float* wp) {
    int i = blockIdx.x * 256 + threadIdx.x;
    if (i >= RN_E9) return;
    const float* s; float* d; int off;
    if      (i < RN_E0) { s = b1; d = g_rB1;   off = 0; }
    else if (i < RN_E1) { s = b2; d = g_rB2;   off = RN_E0; }
    else if (i < RN_E2) { s = wb; d = g_rWb;   off = RN_E1; }
    else if (i < RN_E3) { s = w2; d = g_rW2;   off = RN_E2; }
    else if (i < RN_E4) { s = w3; d = g_rW3;   off = RN_E3; }
    else if (i < RN_E5) { s = f1; d = g_rFc1;  off = RN_E4; }
    else if (i < RN_E6) { s = f2; d = g_rFc2;  off = RN_E5; }
    else if (i < RN_E7) { s = c1; d = g_rCat1; off = RN_E6; }
    else if (i < RN_E8) { s = c2; d = g_rCat2; off = RN_E7; }
    else                { s = wp; d = g_rWp;   off = RN_E8; }
    int j = i - off;
    d[j] = rna_tf32(s[j]);
}

// ---------------- pad x and gW1 ------------------------------------------------
#define PAD_NX (NN * 96)
#define PAD_TOT (PAD_NX + 96 * 128)
__global__ void pad_k(const float* __restrict__ x, const float* __restrict__ w1) {
    int i = blockIdx.x * 256 + threadIdx.x;
    if (i < PAD_NX) {
        int r = i / 96, c = i - r * 96;
        g_xp[i] = (c < 78) ? rna_tf32(x[r * 78 + c]) : 0.0f;
    } else if (i < PAD_TOT) {
        int j = i - PAD_NX;
        int k = j >> 7, n = j & 127;
        g_rW1p[j] = (k < 78) ? rna_tf32(w1[k * 128 + n]) : 0.0f;
    }
}

// ---------------- graph structure ----------------------------------------------
__global__ void edges_k(const int* __restrict__ src, const int* __restrict__ dst, int E) {
    int e = blockIdx.x * blockDim.x + threadIdx.x;
    if (e < E) {
        int d = dst[e];
        atomicAdd(&g_deg[d], 1.0f);
        int pos = atomicAdd(&g_cur[d], 1);
        if (pos < SLOTS) g_slots[d * SLOTS + pos] = src[e];
    }
}

__global__ void gcn_post_k(const float* __restrict__ xw, const float* __restrict__ self,
                           const float* __restrict__ bias, float* __restrict__ out,
                           int F, int dense) {
    int d = blockIdx.x;
    int f = threadIdx.x;
    float rd = rsqrtf(g_deg[d]);
    float acc = self[(long)d * F + f];
    int n = g_cur[d];
    const int* sl = &g_slots[d * SLOTS];
    for (int e = 0; e < n; e++) {
        int s = sl[e];
        acc += xw[(long)s * F + f] * (rsqrtf(g_deg[s]) * rd);
    }
    int row = d;
    if (dense) { int b = d / NPG; row = b * MAXNN + (d - b * NPG); }
    out[(long)row * F + f] = rna_tf32(fmaxf(acc + bias[f], 0.0f));
}

// ---------------- mma / cp.async / TMA / mbarrier helpers ---------------------
__device__ __forceinline__ void mma_tf32(float* c, uint32_t a0, uint32_t a1,
                                         uint32_t a2, uint32_t a3,
                                         uint32_t b0, uint32_t b1) {
    asm volatile(
        "mma.sync.aligned.m16n8k8.row.col.f32.tf32.tf32.f32 "
        "{%0,%1,%2,%3}, {%4,%5,%6,%7}, {%8,%9}, {%0,%1,%2,%3};"
        : "+f"(c[0]), "+f"(c[1]), "+f"(c[2]), "+f"(c[3])
        : "r"(a0), "r"(a1), "r"(a2), "r"(a3), "r"(b0), "r"(b1));
}
__device__ __forceinline__ void cp16(float* dst, const float* src) {
    uint32_t sa = (uint32_t)__cvta_generic_to_shared(dst);
    asm volatile("cp.async.cg.shared.global [%0], [%1], 16;" :: "r"(sa), "l"(src));
}
__device__ __forceinline__ void cp_commit() {
    asm volatile("cp.async.commit_group;");
}
template <int NG> __device__ __forceinline__ void cp_wait() {
    asm volatile("cp.async.wait_group %0;" :: "n"(NG));
}
__device__ __forceinline__ uint32_t s2u(const void* p) {
    return (uint32_t)__cvta_generic_to_shared(p);
}
__device__ __forceinline__ void mbar_init(uint32_t a, uint32_t cnt) {
    asm volatile("mbarrier.init.shared.b64 [%0], %1;" :: "r"(a), "r"(cnt) : "memory");
}
__device__ __forceinline__ void mbar_expect(uint32_t a, uint32_t bytes) {
    asm volatile("mbarrier.arrive.expect_tx.shared.b64 _, [%0], %1;"
                 :: "r"(a), "r"(bytes) : "memory");
}
__device__ __forceinline__ void mbar_wait(uint32_t a, uint32_t parity) {
    asm volatile(
        "{\n\t.reg .pred P1;\n"
        "W_%=:\n\t"
        "mbarrier.try_wait.parity.acquire.cta.shared::cta.b64 P1, [%0], %1;\n\t"
        "@!P1 bra W_%=;\n\t}\n"
        :: "r"(a), "r"(parity) : "memory");
}
__device__ __forceinline__ void tma2d(uint32_t dst, const CUtensorMap* tm,
                                      int cx, int cy, uint32_t mbar) {
    asm volatile(
        "cp.async.bulk.tensor.2d.shared::cta.global.tile.mbarrier::complete_tx::bytes "
        "[%0], [%1, {%2, %3}], [%4];"
        :: "r"(dst), "l"(tm), "r"(cx), "r"(cy), "r"(mbar) : "memory");
}

// ---------------- M128xN128 tf32 GEMM: TMA-A + cp.async-B, 3 stages -----------
// A stage: 128 rows x 32 floats packed (128B rows, SW128 swizzled by TMA) = 16384 B
// B stage: 32 rows x 136 floats (pad)                                    = 17408 B
#define A_ST_F 4096
#define B_ST_F (32 * 136)
#define STG_F (A_ST_F + B_ST_F)               // 8448 floats = 33792 B (33*1024)
#define MB_OFF_B (3 * STG_F * 4)              // 101376
#define TM_SMEM (MB_OFF_B + 64)
#define A_TILE_BYTES 16384

__global__ void __launch_bounds__(256, 2)
gemm_tf32_k(const __grid_constant__ CUtensorMap tmA,
            const float* __restrict__ W,
            const float* __restrict__ bias, float* __restrict__ Cout,
            int M, int K, int N, int act,
            const int* __restrict__ gidx, const int* __restrict__ cntp,
            int fixA, int rndC) {
    const int bm = blockIdx.y << 7, bn = blockIdx.x << 7;
    if (cntp && bm >= cntp[0] * 512) return;

    extern __shared__ __align__(1024) float sm[];
    float* A0 = sm;                 float* B0 = sm + A_ST_F;
    float* A1 = sm + STG_F;         float* B1 = A1 + A_ST_F;
    float* A2 = sm + 2 * STG_F;     float* B2 = A2 + A_ST_F;
    const uint32_t smbase = s2u(sm);
    const uint32_t mb0 = smbase + MB_OFF_B;
    const uint32_t mb1 = mb0 + 8;
    const uint32_t mb2 = mb1 + 8;

    const int tid  = threadIdx.x;
    const int warp = tid >> 5, lane = tid & 31;
    const int wm = (warp & 1) << 6;
    const int wn = (warp >> 1) << 5;
    const int gid = lane >> 2, tig = lane & 3;
    const uint32_t afix = fixA ? 0x1000u : 0u;

    if (tid == 0) { mbar_init(mb0, 1); mbar_init(mb1, 1); mbar_init(mb2, 1); }
    __syncthreads();

    const int rowbase = gidx ? (gidx[bm >> 9] * 512 + (bm & 511)) : bm;

    float acc[4][4][4];
#pragma unroll
    for (int i = 0; i < 4; i++)
#pragma unroll
        for (int j = 0; j < 4; j++)
#pragma unroll
            for (int q = 0; q < 4; q++) acc[i][j][q] = 0.0f;

    // B load coords (4 cp16 per thread)
    int b_k[4], b_n4[4];
#pragma unroll
    for (int i = 0; i < 4; i++) {
        int lin = tid + (i << 8);
        b_k[i] = lin >> 5;
        b_n4[i] = (lin & 31) << 2;
    }
    const int KT = K >> 5;

    auto loadB = [&](int k0, float* Bs) {
#pragma unroll
        for (int i = 0; i < 4; i++)
            cp16(Bs + b_k[i] * 136 + b_n4[i],
                 W + (long)(k0 + b_k[i]) * N + bn + b_n4[i]);
        cp_commit();
    };

    // prologue: stages 0,1
    if (tid == 0) {
        mbar_expect(mb0, A_TILE_BYTES);
        tma2d(s2u(A0), &tmA, 0, rowbase, mb0);
        mbar_expect(mb1, A_TILE_BYTES);
        tma2d(s2u(A1), &tmA, 32, rowbase, mb1);
    }
    loadB(0, B0);
    loadB(32, B1);

    float *Ac = A0, *An = A1, *Af = A2;
    float *Bc = B0, *Bn = B1, *Bf = B2;
    uint32_t mc = mb0, mn = mb1, mf = mb2;
    int par = 0, c3 = 0;

    for (int kt = 0; kt < KT; kt++) {
        cp_wait<1>();          // all B groups except newest done
        __syncthreads();       // prev compute done; stages safe to overwrite
        if (kt + 2 < KT) {
            if (tid == 0) {
                mbar_expect(mf, A_TILE_BYTES);
                tma2d(s2u(Af), &tmA, (kt + 2) << 5, rowbase, mf);
            }
            loadB((kt + 2) << 5, Bf);
        } else {
            cp_commit();       // keep positional accounting aligned
        }
        mbar_wait(mc, (uint32_t)par);

        float* As = Ac;
        float* Bs = Bc;
#pragma unroll
        for (int ks = 0; ks < 4; ks++) {
            const int kk = ks << 3;
            uint32_t bf[4][2];
#pragma unroll
            for (int nt = 0; nt < 4; nt++) {
                int col = wn + (nt << 3) + gid;
                bf[nt][0] = __float_as_uint(Bs[(kk + tig) * 136 + col]);
                bf[nt][1] = __float_as_uint(Bs[(kk + tig + 4) * 136 + col]);
            }
#pragma unroll
            for (int mt = 0; mt < 4; mt++) {
                int r0 = wm + (mt << 4) + gid;
                int r1 = r0 + 8;
                int sw = (r0 & 7) << 2;     // (r0&7)==(r1&7)==(gid&7)
                // SW128: float index = r*32 + (k ^ ((r&7)<<2))
                uint32_t a0 = __float_as_uint(As[(r0 << 5) + ((kk + tig)     ^ sw)]) + afix;
                uint32_t a1 = __float_as_uint(As[(r1 << 5) + ((kk + tig)     ^ sw)]) + afix;
                uint32_t a2 = __float_as_uint(As[(r0 << 5) + ((kk + tig + 4) ^ sw)]) + afix;
                uint32_t a3 = __float_as_uint(As[(r1 << 5) + ((kk + tig + 4) ^ sw)]) + afix;
#pragma unroll
                for (int nt = 0; nt < 4; nt++)
                    mma_tf32(acc[mt][nt], a0, a1, a2, a3, bf[nt][0], bf[nt][1]);
            }
        }
        // rotate
        float* t;
        t = Ac; Ac = An; An = Af; Af = t;
        t = Bc; Bc = Bn; Bn = Bf; Bf = t;
        uint32_t mt2 = mc; mc = mn; mn = mf; mf = mt2;
        if (++c3 == 3) { c3 = 0; par ^= 1; }
    }

#pragma unroll
    for (int mt = 0; mt < 4; mt++) {
        int r0 = bm + wm + (mt << 4) + gid;
#pragma unroll
        for (int nt = 0; nt < 4; nt++) {
            int c = bn + wn + (nt << 3) + (tig << 1);
            float v0 = acc[mt][nt][0], v1 = acc[mt][nt][1];
            float v2 = acc[mt][nt][2], v3 = acc[mt][nt][3];
            if (bias) {
                float b0 = bias[c], b1 = bias[c + 1];
                v0 += b0; v1 += b1; v2 += b0; v3 += b1;
            }
            if (act) {
                v0 = fmaxf(v0, 0.0f); v1 = fmaxf(v1, 0.0f);
                v2 = fmaxf(v2, 0.0f); v3 = fmaxf(v3, 0.0f);
            }
            if (rndC) {
                v0 = rna_tf32(v0); v1 = rna_tf32(v1);
                v2 = rna_tf32(v2); v3 = rna_tf32(v3);
            }
            *(float2*)&Cout[(long)r0 * N + c] = make_float2(v0, v1);
            *(float2*)&Cout[(long)(r0 + 8) * N + c] = make_float2(v2, v3);
        }
    }
}

// ---------------- M64 tf32 GEMM (3-stage, small-grid shapes) — R11 version ----
#define AS_STRIDE 36
#define BS_STRIDE 136
#define ST64 (64 * AS_STRIDE + 32 * BS_STRIDE)
#define G64_SMEM_BYTES (3 * ST64 * 4)

__global__ void __launch_bounds__(256, 2)
gemm64_k(const float* __restrict__ A, const float* __restrict__ W,
         const float* __restrict__ bias, float* __restrict__ Cout,
         int M, int K, int N, int act, int rndC,
         float* __restrict__ C2, const float* __restrict__ degp) {
    const int bm = blockIdx.y << 6, bn = blockIdx.x << 7;

    extern __shared__ float sm[];
    float* Acur = sm;
    float* Bcur = sm + 64 * AS_STRIDE;
    float* Anxt = sm + ST64;
    float* Bnxt = Anxt + 64 * AS_STRIDE;
    float* Afut = sm + 2 * ST64;
    float* Bfut = Afut + 64 * AS_STRIDE;

    const int tid  = threadIdx.x;
    const int warp = tid >> 5, lane = tid & 31;
    const int wm = (warp & 1) << 5;
    const int wn = (warp >> 1) << 5;
    const int gid = lane >> 2, tig = lane & 3;

    float acc[2][4][4];
#pragma unroll
    for (int i = 0; i < 2; i++)
#pragma unroll
        for (int j = 0; j < 4; j++)
#pragma unroll
            for (int q = 0; q < 4; q++) acc[i][j][q] = 0.0f;

    int a_m[2], a_k4[2];
    int b_k[4], b_n4[4];
#pragma unroll
    for (int i = 0; i < 2; i++) {
        int lin = tid + (i << 8);
        a_m[i] = lin >> 3;
        a_k4[i] = (lin & 7) << 2;
    }
#pragma unroll
    for (int i = 0; i < 4; i++) {
        int lin = tid + (i << 8);
        b_k[i] = lin >> 5;
        b_n4[i] = (lin & 31) << 2;
    }

    const int KT = K >> 5;
    auto load_tile = [&](int k0, float* As, float* Bs) {
#pragma unroll
        for (int i = 0; i < 2; i++)
            cp16(As + a_m[i] * AS_STRIDE + a_k4[i],
                 A + (long)(bm + a_m[i]) * K + k0 + a_k4[i]);
#pragma unroll
        for (int i = 0; i < 4; i++)
            cp16(Bs + b_k[i] * BS_STRIDE + b_n4[i],
                 W + (long)(k0 + b_k[i]) * N + bn + b_n4[i]);
        cp_commit();
    };

    load_tile(0, Acur, Bcur);
    load_tile(32, Anxt, Bnxt);

    for (int kt = 0; kt < KT; kt++) {
        cp_wait<1>();
        __syncthreads();
        if (kt + 2 < KT) load_tile((kt + 2) << 5, Afut, Bfut);
        else             cp_commit();
        float* As = Acur;
        float* Bs = Bcur;

#pragma unroll
        for (int ks = 0; ks < 4; ks++) {
            const int kk = ks << 3;
            uint32_t bf[4][2];
#pragma unroll
            for (int nt = 0; nt < 4; nt++) {
                int col = wn + (nt << 3) + gid;
                bf[nt][0] = __float_as_uint(Bs[(kk + tig) * BS_STRIDE + col]);
                bf[nt][1] = __float_as_uint(Bs[(kk + tig + 4) * BS_STRIDE + col]);
            }
#pragma unroll
            for (int mt = 0; mt < 2; mt++) {
                int row = wm + (mt << 4) + gid;
                uint32_t a0 = __float_as_uint(As[row * AS_STRIDE + kk + tig]);
                uint32_t a1 = __float_as_uint(As[(row + 8) * AS_STRIDE + kk + tig]);
                uint32_t a2 = __float_as_uint(As[row * AS_STRIDE + kk + tig + 4]);
                uint32_t a3 = __float_as_uint(As[(row + 8) * AS_STRIDE + kk + tig + 4]);
#pragma unroll
                for (int nt = 0; nt < 4; nt++)
                    mma_tf32(acc[mt][nt], a0, a1, a2, a3, bf[nt][0], bf[nt][1]);
            }
        }
        float* ta = Acur; Acur = Anxt; Anxt = Afut; Afut = ta;
        float* tb = Bcur; Bcur = Bnxt; Bnxt = Bfut; Bfut = tb;
    }

#pragma unroll
    for (int mt = 0; mt < 2; mt++) {
        int r0 = bm + wm + (mt << 4) + gid;
        float id0 = 0.0f, id1 = 0.0f;
        if (C2) { id0 = 1.0f / degp[r0]; id1 = 1.0f / degp[r0 + 8]; }
#pragma unroll
        for (int nt = 0; nt < 4; nt++) {
            int c = bn + wn + (nt << 3) + (tig << 1);
            float v0 = acc[mt][nt][0], v1 = acc[mt][nt][1];
            float v2 = acc[mt][nt][2], v3 = acc[mt][nt][3];
            if (bias) {
                float b0 = bias[c], b1 = bias[c + 1];
                v0 += b0; v1 += b1; v2 += b0; v3 += b1;
            }
            if (act) {
                v0 = fmaxf(v0, 0.0f); v1 = fmaxf(v1, 0.0f);
                v2 = fmaxf(v2, 0.0f); v3 = fmaxf(v3, 0.0f);
            }
            if (rndC) {
                v0 = rna_tf32(v0); v1 = rna_tf32(v1);
                v2 = rna_tf32(v2); v3 = rna_tf32(v3);
            }
            *(float2*)&Cout[(long)r0 * N + c] = make_float2(v0, v1);
            *(float2*)&Cout[(long)(r0 + 8) * N + c] = make_float2(v2, v3);
            if (C2) {
                *(float2*)&C2[(long)r0 * N + c] = make_float2(v0 * id0, v1 * id0);
                *(float2*)&C2[(long)(r0 + 8) * N + c] = make_float2(v2 * id1, v3 * id1);
            }
        }
    }
}

// ---------------- co-attention: C via tensor cores ----------------------------
#define CC_SMEM ((128 * 132 + 64 * 132) * 4)
__global__ void __launch_bounds__(256)
coattC_mma_k(const float* __restrict__ TW, const float* __restrict__ hd,
             float* __restrict__ C) {
    int b = blockIdx.y;
    int l0 = blockIdx.x << 7;
    int slot = g_map[b];
    extern __shared__ float sm[];
    float* As = sm;
    float* Bs = sm + 128 * 132;
    int tid = threadIdx.x;

    const float* Ab = TW + ((long)slot * 512 + l0) * 128;
    for (int i = tid; i < 128 * 32; i += 256) {
        int r = i >> 5, c4 = (i & 31) << 2;
        *(float4*)&As[r * 132 + c4] = *(const float4*)(Ab + r * 128 + c4);
    }
    const float* Bb = hd + (long)b * 45 * 128;
    for (int i = tid; i < 64 * 32; i += 256) {
        int r = i >> 5, c4 = (i & 31) << 2;
        float4 v = make_float4(0.f, 0.f, 0.f, 0.f);
        if (r < 45) v = *(const float4*)(Bb + r * 128 + c4);
        *(float4*)&Bs[r * 132 + c4] = v;
    }
    __syncthreads();

    int warp = tid >> 5, lane = tid & 31;
    int wm = (warp & 1) << 6;
    int wn = (warp >> 1) << 4;
    int gid = lane >> 2, tig = lane & 3;
    float acc[4][2][4];
#pragma unroll
    for (int i = 0; i < 4; i++)
#pragma unroll
        for (int j = 0; j < 2; j++)
#pragma unroll
            for (int q = 0; q < 4; q++) acc[i][j][q] = 0.0f;

#pragma unroll
    for (int kk = 0; kk < 128; kk += 8) {
        uint32_t bf[2][2];
#pragma unroll
        for (int nt = 0; nt < 2; nt++) {
            int col = wn + (nt << 3) + gid;
            bf[nt][0] = __float_as_uint(Bs[col * 132 + kk + tig]);
            bf[nt][1] = __float_as_uint(Bs[col * 132 + kk + tig + 4]);
        }
#pragma unroll
        for (int mt = 0; mt < 4; mt++) {
            int row = wm + (mt << 4) + gid;
            uint32_t a0 = __float_as_uint(As[row * 132 + kk + tig]);
            uint32_t a1 = __float_as_uint(As[(row + 8) * 132 + kk + tig]);
            uint32_t a2 = __float_as_uint(As[row * 132 + kk + tig + 4]);
            uint32_t a3 = __float_as_uint(As[(row + 8) * 132 + kk + tig + 4]);
#pragma unroll
            for (int nt = 0; nt < 2; nt++)
                mma_tf32(acc[mt][nt], a0, a1, a2, a3, bf[nt][0], bf[nt][1]);
        }
    }

#pragma unroll
    for (int mt = 0; mt < 4; mt++) {
        int l = l0 + wm + (mt << 4) + gid;
        float* d0 = &C[((long)b * 512 + l) * 45];
        float* d8 = &C[((long)b * 512 + l + 8) * 45];
#pragma unroll
        for (int nt = 0; nt < 2; nt++) {
            int s = wn + (nt << 3) + (tig << 1);
            if (s < 45)     d0[s]     = tanhf(acc[mt][nt][0]);
            if (s + 1 < 45) d0[s + 1] = tanhf(acc[mt][nt][1]);
            if (s < 45)     d8[s]     = tanhf(acc[mt][nt][2]);
            if (s + 1 < 45) d8[s + 1] = tanhf(acc[mt][nt][3]);
        }
    }
}

// ---------------- co-attention: Wpt per distinct protein slot -----------------
#define WP_SMEM ((128 * 132 + 32 * 132) * 4)
__global__ void __launch_bounds__(256)
wptslot_mma_k(const float* __restrict__ t2, const float* __restrict__ Wp,
              float* __restrict__ Wpt) {
    int slot = blockIdx.y;
    if (slot >= g_cnt[0]) return;
    int l0 = blockIdx.x << 7;
    extern __shared__ float sm[];
    float* As = sm;
    float* Bs = sm + 128 * 132;
    int tid = threadIdx.x;

    const float* Ab = t2 + ((long)slot * 512 + l0) * 128;
    for (int i = tid; i < 128 * 32; i += 256) {
        int r = i >> 5, c4 = (i & 31) << 2;
        *(float4*)&As[r * 132 + c4] = *(const float4*)(Ab + r * 128 + c4);
    }
    for (int i = tid; i < 32 * 32; i += 256) {
        int r = i >> 5, c4 = (i & 31) << 2;
        *(float4*)&Bs[r * 132 + c4] = *(const float4*)(Wp + r * 128 + c4);
    }
    __syncthreads();

    int warp = tid >> 5, lane = tid & 31;
    int wm = (warp & 1) << 6;
    int wn = (warp >> 1) << 3;
    int gid = lane >> 2, tig = lane & 3;
    float acc[4][4];
#pragma unroll
    for (int i = 0; i < 4; i++)
#pragma unroll
        for (int q = 0; q < 4; q++) acc[i][q] = 0.0f;

#pragma unroll
    for (int kk = 0; kk < 128; kk += 8) {
        int col = wn + gid;
        uint32_t b0 = __float_as_uint(Bs[col * 132 + kk + tig]);
        uint32_t b1 = __float_as_uint(Bs[col * 132 + kk + tig + 4]);
#pragma unroll
        for (int mt = 0; mt < 4; mt++) {
            int row = wm + (mt << 4) + gid;
            uint32_t a0 = __float_as_uint(As[row * 132 + kk + tig]);
            uint32_t a1 = __float_as_uint(As[(row + 8) * 132 + kk + tig]);
            uint32_t a2 = __float_as_uint(As[row * 132 + kk + tig + 4]);
            uint32_t a3 = __float_as_uint(As[(row + 8) * 132 + kk + tig + 4]);
            mma_tf32(acc[mt], a0, a1, a2, a3, b0, b1);
        }
    }

#pragma unroll
    for (int mt = 0; mt < 4; mt++) {
        int l = l0 + wm + (mt << 4) + gid;
        int n = wn + (tig << 1);
        Wpt[((long)slot * 32 + n)     * 512 + l]     = acc[mt][0];
        Wpt[((long)slot * 32 + n + 1) * 512 + l]     = acc[mt][1];
        Wpt[((long)slot * 32 + n)     * 512 + l + 8] = acc[mt][2];
        Wpt[((long)slot * 32 + n + 1) * 512 + l + 8] = acc[mt][3];
    }
}

// Wcx[b,k,s] = sum_m W_c[k,m] * hd[b,s,m]
__global__ void __launch_bounds__(256)
wcx_k(const float* __restrict__ Wc, const float* __restrict__ hd,
      float* __restrict__ Wcx) {
    int b = blockIdx.x;
    __shared__ float Wcs[32][132];
    __shared__ float hds[45][132];
    int tid = threadIdx.x;
    for (int idx = tid; idx < 32 * 32; idx += 256) {
        int r = idx >> 5, c = (idx & 31) << 2;
        float4 v = *(const float4*)(Wc + r * 128 + c);
        Wcs[r][c] = v.x; Wcs[r][c + 1] = v.y; Wcs[r][c + 2] = v.z; Wcs[r][c + 3] = v.w;
    }
    const float* hdb = hd + (long)b * 45 * 128;
    for (int idx = tid; idx < 45 * 32; idx += 256) {
        int r = idx >> 5, c = (idx & 31) << 2;
        float4 v = *(const float4*)(hdb + r * 128 + c);
        hds[r][c] = v.x; hds[r][c + 1] = v.y; hds[r][c + 2] = v.z; hds[r][c + 3] = v.w;
    }
    __syncthreads();
    for (int o = tid; o < 32 * 45; o += 256) {
        int k = o / 45, s = o - k * 45;
        float a = 0.0f;
        for (int m = 0; m < 128; m += 4) {
            float4 wv = *(const float4*)&Wcs[k][m];
            float4 hv = *(const float4*)&hds[s][m];
            a += wv.x * hv.x + wv.y * hv.y + wv.z * hv.z + wv.w * hv.w;
        }
        Wcx[((long)b * 32 + k) * 45 + s] = a;
    }
}

// Hc[b,k,s] = tanh(Wcx[b,k,s] + sum_l Wpt[slot,k,l]*C[b,l,s])
__global__ void __launch_bounds__(256)
hc_k(const float* __restrict__ Wpt, const float* __restrict__ C,
     const float* __restrict__ Wcx, float* __restrict__ Hc) {
    int b = blockIdx.x;
    int slot = g_map[b];
    __shared__ float Cc[64][48];
    __shared__ float Wptc[32][64];
    int tid = threadIdx.x;
    float acc[6] = {0, 0, 0, 0, 0, 0};
    for (int lc = 0; lc < 512; lc += 64) {
        for (int idx = tid; idx < 32 * 64; idx += 256) {
            int k = idx >> 6, li = idx & 63;
            Wptc[k][li] = Wpt[((long)slot * 32 + k) * 512 + lc + li];
        }
        for (int idx = tid; idx < 64 * 48; idx += 256) {
            int li = idx / 48, s = idx - li * 48;
            Cc[li][s] = (s < 45) ? C[((long)b * 512 + lc + li) * 45 + s] : 0.0f;
        }
        __syncthreads();
#pragma unroll
        for (int i = 0; i < 6; i++) {
            int o = tid + (i << 8);
            if (o < 32 * 45) {
                int k = o / 45, s = o - k * 45;
                float a = acc[i];
#pragma unroll 8
                for (int li = 0; li < 64; li++) a += Wptc[k][li] * Cc[li][s];
                acc[i] = a;
            }
        }
        __syncthreads();
    }
#pragma unroll
    for (int i = 0; i < 6; i++) {
        int o = tid + (i << 8);
        if (o < 32 * 45) {
            int k = o / 45, s = o - k * 45;
            long idx = ((long)b * 32 + k) * 45 + s;
            Hc[idx] = tanhf(acc[i] + Wcx[idx]);
        }
    }
}

// Hp[b,k,l] = tanh(Wpt[slot,k,l] + sum_s Wcx[b,k,s]*C[b,l,s])
__global__ void __launch_bounds__(256)
hp_k(const float* __restrict__ Wpt, const float* __restrict__ C,
     const float* __restrict__ Wcx, float* __restrict__ Hp) {
    int b = blockIdx.y;
    int slot = g_map[b];
    int l0 = blockIdx.x << 7;
    __shared__ float Wcxs[32][48];
    __shared__ float Cs[128][48];
    int tid = threadIdx.x;
    for (int idx = tid; idx < 32 * 48; idx += 256) {
        int k = idx / 48, s = idx - k * 48;
        Wcxs[k][s] = (s < 45) ? Wcx[((long)b * 32 + k) * 45 + s] : 0.0f;
    }
    for (int idx = tid; idx < 128 * 48; idx += 256) {
        int li = idx / 48, s = idx - li * 48;
        Cs[li][s] = (s < 45) ? C[((long)b * 512 + l0 + li) * 45 + s] : 0.0f;
    }
    __syncthreads();
#pragma unroll
    for (int i = 0; i < 16; i++) {
        int o = tid + (i << 8);
        int k = o >> 7, l = o & 127;
        float a = Wpt[((long)slot * 32 + k) * 512 + l0 + l];
#pragma unroll 8
        for (int s = 0; s < 48; s++) a += Wcxs[k][s] * Cs[l][s];
        Hp[((long)b * 32 + k) * 512 + l0 + l] = tanhf(a);
    }
}

__global__ void ac_k(const float* __restrict__ Hc, const float* __restrict__ whc,
                     float* __restrict__ ac) {
    int b = blockIdx.x, s = threadIdx.x;
    __shared__ float red[64];
    float v = -3.0e38f;
    if (s < 45) {
        float a = 0.0f;
#pragma unroll
        for (int k = 0; k < 32; k++) a += whc[k] * Hc[((long)b * 32 + k) * 45 + s];
        v = a;
    }
    red[s] = v;
    __syncthreads();
    for (int off = 32; off > 0; off >>= 1) {
        if (s < off) red[s] = fmaxf(red[s], red[s + off]);
        __syncthreads();
    }
    float mx = red[0];
    __syncthreads();
    float e = (s < 45) ? expf(v - mx) : 0.0f;
    red[s] = e;
    __syncthreads();
    for (int off = 32; off > 0; off >>= 1) {
        if (s < off) red[s] += red[s + off];
        __syncthreads();
    }
    float inv = 1.0f / red[0];
    if (s < 45) ac[b * 45 + s] = e * inv;
}

__global__ void ap_k(const float* __restrict__ Hp, const float* __restrict__ whp,
                     float* __restrict__ ap) {
    int b = blockIdx.x, t = threadIdx.x;
    __shared__ float red[256];
    float v0 = 0.0f, v1 = 0.0f;
#pragma unroll
    for (int k = 0; k < 32; k++) {
        const float* row = Hp + ((long)b * 32 + k) * 512;
        float w = whp[k];
        v0 += w * row[t];
        v1 += w * row[t + 256];
    }
    red[t] = fmaxf(v0, v1);
    __syncthreads();
    for (int off = 128; off > 0; off >>= 1) {
        if (t < off) red[t] = fmaxf(red[t], red[t + off]);
        __syncthreads();
    }
    float mx = red[0];
    __syncthreads();
    float e0 = expf(v0 - mx), e1 = expf(v1 - mx);
    red[t] = e0 + e1;
    __syncthreads();
    for (int off = 128; off > 0; off >>= 1) {
        if (t < off) red[t] += red[t + off];
        __syncthreads();
    }
    float inv = 1.0f / red[0];
    ap[b * 512 + t] = e0 * inv;
    ap[b * 512 + t + 256] = e1 * inv;
}

__global__ void cp_k(const float* __restrict__ ac, const float* __restrict__ ap,
                     const float* __restrict__ hd, const float* __restrict__ t2,
                     float* __restrict__ cp) {
    int b = blockIdx.x, m = threadIdx.x;
    int slot = g_map[b];
    __shared__ float acs[45];
    __shared__ float aps[512];
    if (m < 45) acs[m] = ac[b * 45 + m];
    for (int i = m; i < 512; i += 128) aps[i] = ap[b * 512 + i];
    __syncthreads();
    float c = 0.0f;
    for (int s = 0; s < 45; s++) c += acs[s] * hd[((long)b * 45 + s) * 128 + m];
    const float* t2b = t2 + (long)slot * 512 * 128;
    float p = 0.0f;
    for (int l = 0; l < 512; l++) p += aps[l] * t2b[l * 128 + m];
    cp[b * 256 + m] = rna_tf32(c);
    cp[b * 256 + 128 + m] = rna_tf32(p);
}

__global__ void out_k(const float* __restrict__ c2, const float* __restrict__ outW,
                      const float* __restrict__ outb, float* __restrict__ out) {
    int b = blockIdx.x, t = threadIdx.x;
    __shared__ float red[128];
    float v = 0.0f;
    for (int i = t; i < 512; i += 128) v += c2[b * 512 + i] * outW[i];
    red[t] = v;
    __syncthreads();
    for (int off = 64; off > 0; off >>= 1) {
        if (t < off) red[t] += red[t + off];
        __syncthreads();
    }
    if (t == 0) out[b] = red[0] + outb[0];
}

// ---------------- host side ---------------------------------------------------
static inline float* symaddr(const void* sym) {
    void* p = nullptr;
    cudaGetSymbolAddress(&p, sym);
    return (float*)p;
}
static inline int* symaddri(const void* sym) {
    void* p = nullptr;
    cudaGetSymbolAddress(&p, sym);
    return (int*)p;
}

// driver entry point for cuTensorMapEncodeTiled without -lcuda
typedef CUresult (*PFN_tmEncode)(
    CUtensorMap*, CUtensorMapDataType, unsigned int, void*,
    const unsigned long long*, const unsigned long long*,
    const unsigned int*, const unsigned int*,
    CUtensorMapInterleave, CUtensorMapSwizzle,
    CUtensorMapL2promotion, CUtensorMapFloatOOBfill);

static PFN_tmEncode tm_encode() {
    static PFN_tmEncode fn = nullptr;
    if (!fn) {
        void* p = nullptr;
        cudaDriverEntryPointQueryResult st;
        cudaGetDriverEntryPointByVersion("cuTensorMapEncodeTiled", &p, 12000,
                                         cudaEnableDefault, &st);
        fn = (PFN_tmEncode)p;
    }
    return fn;
}

static inline void make_tmA(CUtensorMap* tm, const float* A, long nrows, int K) {
    unsigned long long dims[2]    = {(unsigned long long)K, (unsigned long long)nrows};
    unsigned long long strides[1] = {(unsigned long long)K * 4};
    unsigned int box[2]  = {32u, 128u};
    unsigned int estr[2] = {1u, 1u};
    tm_encode()(tm, CU_TENSOR_MAP_DATA_TYPE_FLOAT32, 2, (void*)A,
                dims, strides, box, estr,
                CU_TENSOR_MAP_INTERLEAVE_NONE, CU_TENSOR_MAP_SWIZZLE_128B,
                CU_TENSOR_MAP_L2_PROMOTION_L2_128B, CU_TENSOR_MAP_FLOAT_OOB_FILL_NONE);
}

static inline void gemm_tc(const float* A, long nrowsA, const float* W,
                           const float* bias, float* C,
                           int M, int K, int N, int act,
                           const int* gidx, const int* cntp, int fixA, int rndC) {
    CUtensorMap tm;
    make_tmA(&tm, A, nrowsA, K);
    dim3 g(N >> 7, M >> 7);
    gemm_tf32_k<<<g, 256, TM_SMEM>>>(tm, W, bias, C, M, K, N, act,
                                     gidx, cntp, fixA, rndC);
}
static inline void gemm64(const float* A, const float* W, const float* bias, float* C,
                          int M, int K, int N, int act, int rndC,
                          float* C2 = nullptr, const float* degp = nullptr) {
    dim3 g(N >> 7, M >> 6);
    gemm64_k<<<g, 256, G64_SMEM_BYTES>>>(A, W, bias, C, M, K, N, act, rndC, C2, degp);
}

extern "C" void kernel_launch(void* const* d_in, const int* in_sizes, int n_in,
                              void* d_out, int out_size) {
    const float* x      = (const float*)d_in[0];
    const int*   ei     = (const int*)d_in[1];
    const int*   tgt    = (const int*)d_in[2];
    const float* prot   = (const float*)d_in[4];
    const float* gW1    = (const float*)d_in[5];
    const float* gb1    = (const float*)d_in[6];
    const float* gW2    = (const float*)d_in[7];
    const float* gb2    = (const float*)d_in[8];
    const float* gW3    = (const float*)d_in[9];
    const float* gb3    = (const float*)d_in[10];
    const float* fc1W   = (const float*)d_in[11];
    const float* fc1b   = (const float*)d_in[12];
    const float* fc2W   = (const float*)d_in[13];
    const float* fc2b   = (const float*)d_in[14];
    const float* bert1W = (const float*)d_in[15];
    const float* bert1b = (const float*)d_in[16];
    const float* bert2W = (const float*)d_in[17];
    const float* bert2b = (const float*)d_in[18];
    const float* W_b    = (const float*)d_in[19];
    const float* W_c    = (const float*)d_in[20];
    const float* W_p    = (const float*)d_in[21];
    const float* w_hc   = (const float*)d_in[22];
    const float* w_hp   = (const float*)d_in[23];
    const float* cat1W  = (const float*)d_in[24];
    const float* cat1b  = (const float*)d_in[25];
    const float* cat2W  = (const float*)d_in[26];
    const float* cat2b  = (const float*)d_in[27];
    const float* outW   = (const float*)d_in[28];
    const float* outb   = (const float*)d_in[29];
    float* out = (float*)d_out;

    const int E = in_sizes[1] / 2;
    const int* src  = ei;
    const int* dstp = ei + E;

    float* p_deg    = symaddr(g_deg);
    float* p_xw     = symaddr(g_xw);
    float* p_ha     = symaddr(g_ha);
    float* p_hb     = symaddr(g_hb);
    float* p_xp     = symaddr(g_xp);
    float* p_hdense = symaddr(g_hdense);
    float* p_fc     = symaddr(g_fc);
    float* p_hd     = symaddr(g_hd);
    float* p_t1     = symaddr(g_t1);
    float* p_t2     = symaddr(g_t2);
    float* p_C      = symaddr(g_C);
    float* p_Wcx    = symaddr(g_Wcx);
    float* p_Wpt    = symaddr(g_Wpt);
    float* p_Hc     = symaddr(g_Hc);
    float* p_Hp     = symaddr(g_Hp);
    float* p_ac     = symaddr(g_ac);
    float* p_ap     = symaddr(g_ap);
    float* p_cp     = symaddr(g_cp);
    float* p_c1     = symaddr(g_c1);
    float* p_c2     = symaddr(g_c2);
    int*   p_pid    = symaddri(g_pid_of_slot);
    int*   p_cnt    = symaddri(g_cnt);
    float* p_rB1    = symaddr(g_rB1);
    float* p_rB2    = symaddr(g_rB2);
    float* p_rWb    = symaddr(g_rWb);
    float* p_rW2    = symaddr(g_rW2);
    float* p_rW3    = symaddr(g_rW3);
    float* p_rFc1   = symaddr(g_rFc1);
    float* p_rFc2   = symaddr(g_rFc2);
    float* p_rCat1  = symaddr(g_rCat1);
    float* p_rCat2  = symaddr(g_rCat2);
    float* p_rWp    = symaddr(g_rWp);
    float* p_rW1p   = symaddr(g_rW1p);

    cudaFuncSetAttribute(gemm_tf32_k, cudaFuncAttributeMaxDynamicSharedMemorySize,
                         TM_SMEM);
    cudaFuncSetAttribute(gemm64_k, cudaFuncAttributeMaxDynamicSharedMemorySize,
                         G64_SMEM_BYTES);
    cudaFuncSetAttribute(coattC_mma_k, cudaFuncAttributeMaxDynamicSharedMemorySize,
                         CC_SMEM);
    cudaFuncSetAttribute(wptslot_mma_k, cudaFuncAttributeMaxDynamicSharedMemorySize,
                         WP_SMEM);

    // 1: dedup + deg/cursor init
    prep_k<<<20, 256>>>(tgt);
    // 2: weight rna rounding
    rndall_k<<<(RN_E9 + 255) / 256, 256>>>(bert1W, bert2W, W_b, gW2, gW3,
                                           fc1W, fc2W, cat1W, cat2W, W_p);
    // 3: pad+round x and gW1
    pad_k<<<(PAD_TOT + 255) / 256, 256>>>(x, gW1);
    // 4: bert1 (ncu window target) — TMA-A + dedup'd gather
    gemm_tc(prot, (long)NPROT * LPP, p_rB1, bert1b, p_t1,
            BB * LPP, PROTD, 128, 1, p_pid, p_cnt, 1, 1);
    // 5: graph structure
    edges_k<<<(E + 255) / 256, 256>>>(src, dstp, E);

    // GCN layer 1 (tensor, K=96 padded) + gather-post
    gemm64(p_xp, p_rW1p, nullptr, p_xw, NN, 96, 128, 0, 0, p_ha, p_deg);
    gcn_post_k<<<NN, 128>>>(p_xw, p_ha, gb1, p_hb, 128, 0);

    // protein chain continues (TMA-A path)
    gemm_tc(p_t1, (long)BB * LPP, p_rB2, bert2b, p_t2,
            BB * LPP, 128, 128, 1, nullptr, p_cnt, 0, 1);
    gemm_tc(p_t2, (long)BB * LPP, p_rWb, nullptr, p_t1,
            BB * LPP, 128, 128, 0, nullptr, p_cnt, 0, 1);

    // GCN layer 2
    gemm64(p_hb, p_rW2, nullptr, p_xw, NN, 128, 128, 0, 0, p_ha, p_deg);
    gcn_post_k<<<NN, 128>>>(p_xw, p_ha, gb2, p_ha, 128, 0);
    // GCN layer 3 (writes straight into dense layout)
    gemm64(p_ha, p_rW3, nullptr, p_xw, NN, 128, 256, 0, 0, p_hb, p_deg);
    gcn_post_k<<<NN, 256>>>(p_xw, p_hb, gb3, p_hdense, 256, 1);

    // graph FC stack
    gemm_tc(p_hdense, (long)BB * MAXNN, p_rFc1, fc1b, p_fc,
            BB * MAXNN, 256, 1024, 1, nullptr, nullptr, 0, 1);
    gemm64(p_fc, p_rFc2, fc2b, p_hd, BB * MAXNN, 1024, 128, 1, 1);

    // co-attention
    coattC_mma_k<<<dim3(4, BB), 256, CC_SMEM>>>(p_t1, p_hd, p_C);
    wptslot_mma_k<<<dim3(4, BB), 256, WP_SMEM>>>(p_t2, p_rWp, p_Wpt);
    wcx_k<<<BB, 256>>>(W_c, p_hd, p_Wcx);
    hc_k<<<BB, 256>>>(p_Wpt, p_C, p_Wcx, p_Hc);
    hp_k<<<dim3(4, BB), 256>>>(p_Wpt, p_C, p_Wcx, p_Hp);
    ac_k<<<BB, 64>>>(p_Hc, w_hc, p_ac);
    ap_k<<<BB, 256>>>(p_Hp, w_hp, p_ap);
    cp_k<<<BB, 128>>>(p_ac, p_ap, p_hd, p_t2, p_cp);

    // head
    gemm64(p_cp, p_rCat1, cat1b, p_c1, BB, 256, 1024, 1, 1);
    gemm64(p_c1, p_rCat2, cat2b, p_c2, BB, 1024, 512, 1, 0);
    out_k<<<BB, 128>>>(p_c2, outW, outb, out);
}